// round 10
// baseline (speedup 1.0000x reference)
#include <cuda_runtime.h>
#include <cuda_fp16.h>
#include <cstdint>

// ============================================================================
// Single-term fp16 mma.sync implicit-GEMM conv, round 10.
// Same math as round 8 (D = ah*bh, A=w*64 fp16, B=x fp16, rel_err ~2.9e-4).
// BM=256 x BN=128 per CTA, 512 threads (16 warps, 4m x 4n): one CTA covers
// two former bm tiles, halving B-gather LDG dispatch per unit output.
// BK=32 (round-9 lesson: keep register pressure flat). R8 pipeline order:
// LDG(ch+1) -> MMA(ch) -> STS(ch+1).
// ============================================================================

#define KTOT   2304
#define KCH    72            // 2304 / 32
#define NPIMG  2916
#define OUTIMG (512*NPIMG)
#define XIMG   (256*3136)

#define A_SUB       8192     // one 128-row A subtile (128 x 64B)
#define STAGE_BYTES 24576    // A 16KB (two 128-row blocks) + B 8KB
#define OFF_B       16384
#define OFF_KOFF    49152                  // after 2 stages
#define SMEM_BYTES  (OFF_KOFF + KTOT*4)    // 58368

// A (scaled x64, fp16) in swizzled subtile layout: [mt(4)][ch(72)][8KB]
__device__ __align__(16) unsigned char g_asplit[4ull*72*8192];    // 2.4MB
// x as fp16
__device__ __align__(16) __half g_xh[32 * 256 * 56 * 56];         // 51.4MB

// ---------------------------------------------------------------------------
__device__ __forceinline__ uint32_t smem_u32(const void* p) {
    uint32_t a;
    asm("{ .reg .u64 t; cvta.to.shared.u64 t, %1; cvt.u32.u64 %0, t; }"
        : "=r"(a) : "l"(p));
    return a;
}
__device__ __forceinline__ void sts64(uint32_t addr, uint32_t a, uint32_t b) {
    asm volatile("st.shared.v2.b32 [%0], {%1, %2};" :: "r"(addr), "r"(a), "r"(b));
}
__device__ __forceinline__ void ldsm4(uint32_t a, uint32_t& r0, uint32_t& r1,
                                      uint32_t& r2, uint32_t& r3) {
    asm volatile("ldmatrix.sync.aligned.m8n8.x4.shared.b16 {%0,%1,%2,%3}, [%4];"
                 : "=r"(r0), "=r"(r1), "=r"(r2), "=r"(r3) : "r"(a));
}
__device__ __forceinline__ void mma_f16(float* c, const uint32_t* a,
                                        uint32_t b0, uint32_t b1) {
    asm volatile(
        "mma.sync.aligned.m16n8k16.row.col.f32.f16.f16.f32 "
        "{%0,%1,%2,%3}, {%4,%5,%6,%7}, {%8,%9}, {%0,%1,%2,%3};"
        : "+f"(c[0]), "+f"(c[1]), "+f"(c[2]), "+f"(c[3])
        : "r"(a[0]), "r"(a[1]), "r"(a[2]), "r"(a[3]), "r"(b0), "r"(b1));
}
__device__ __forceinline__ void cpasync16(uint32_t dst, const void* src) {
    asm volatile("cp.async.cg.shared.global [%0], [%1], 16;"
                 :: "r"(dst), "l"(src) : "memory");
}
__device__ __forceinline__ void cp_commit() {
    asm volatile("cp.async.commit_group;" ::: "memory");
}
__device__ __forceinline__ void cp_wait0() {
    asm volatile("cp.async.wait_group 0;" ::: "memory");
}

// ---------------------------------------------------------------------------
// prep kernels (unchanged)
// ---------------------------------------------------------------------------
__global__ void pack_x_kernel(const float* __restrict__ x) {
    int i = blockIdx.x * blockDim.x + threadIdx.x;   // 6422528 total
    float4 v = ((const float4*)x)[i];
    __half h0 = __float2half_rn(v.x), h1 = __float2half_rn(v.y);
    __half h2 = __float2half_rn(v.z), h3 = __float2half_rn(v.w);
    uint32_t w0 = (uint32_t)*(uint16_t*)&h0 | ((uint32_t)*(uint16_t*)&h1 << 16);
    uint32_t w1 = (uint32_t)*(uint16_t*)&h2 | ((uint32_t)*(uint16_t*)&h3 << 16);
    ((uint2*)g_xh)[i] = make_uint2(w0, w1);
}
__global__ void prep_a(const float* __restrict__ w) {
    int i = blockIdx.x * 256 + threadIdx.x;          // 147456 total
    int co = i / 288;
    int r  = i - co * 288;
    int ch = r >> 2, kq = r & 3;
    const float4* p = (const float4*)(w + (size_t)co * KTOT + ch * 32 + kq * 8);
    float4 v0 = p[0], v1 = p[1];
    __half a0 = __float2half_rn(v0.x * 64.f), a1 = __float2half_rn(v0.y * 64.f);
    __half a2 = __float2half_rn(v0.z * 64.f), a3 = __float2half_rn(v0.w * 64.f);
    __half a4 = __float2half_rn(v1.x * 64.f), a5 = __float2half_rn(v1.y * 64.f);
    __half a6 = __float2half_rn(v1.z * 64.f), a7 = __float2half_rn(v1.w * 64.f);
    uint32_t h0 = (uint32_t)*(uint16_t*)&a0 | ((uint32_t)*(uint16_t*)&a1 << 16);
    uint32_t h1 = (uint32_t)*(uint16_t*)&a2 | ((uint32_t)*(uint16_t*)&a3 << 16);
    uint32_t h2 = (uint32_t)*(uint16_t*)&a4 | ((uint32_t)*(uint16_t*)&a5 << 16);
    uint32_t h3 = (uint32_t)*(uint16_t*)&a6 | ((uint32_t)*(uint16_t*)&a7 << 16);
    int m = co & 127;
    size_t base = ((size_t)(co >> 7) * 72 + ch) * A_SUB
                + m * 64 + (((uint32_t)kq * 16) ^ ((((uint32_t)m >> 1) & 3) << 4));
    *(uint4*)(g_asplit + base) = make_uint4(h0, h1, h2, h3);
}

// ---------------------------------------------------------------------------
// B producer: thread -> (row n = tid>>2, kq = tid&3 -> 8 k's).
// 8 LDG.16 + 2 STS.64 per thread per chunk.
// ---------------------------------------------------------------------------
__device__ __forceinline__ void load_b(
    int ch, const __half* xb, uint32_t koffs, int kq, uint16_t (&bx)[8])
{
    const uint32_t kb4 = koffs + (uint32_t)(ch * 32 + kq * 8) * 4;
    #pragma unroll
    for (int g = 0; g < 2; ++g) {
        uint32_t k0, k1, k2, k3;
        asm volatile("ld.shared.v4.b32 {%0,%1,%2,%3}, [%4];"
                     : "=r"(k0), "=r"(k1), "=r"(k2), "=r"(k3)
                     : "r"(kb4 + g * 16));
        bx[4*g+0] = *(const uint16_t*)(xb + k0);
        bx[4*g+1] = *(const uint16_t*)(xb + k1);
        bx[4*g+2] = *(const uint16_t*)(xb + k2);
        bx[4*g+3] = *(const uint16_t*)(xb + k3);
    }
}
__device__ __forceinline__ void store_b(
    uint32_t bufb, const uint16_t (&bx)[8], int prow, int kq, uint32_t pswz)
{
    const uint32_t sB = bufb + OFF_B + (uint32_t)prow * 64;
    const uint32_t kobase = (uint32_t)kq * 16;
    #pragma unroll
    for (int g = 0; g < 2; ++g) {
        uint32_t w0 = (uint32_t)bx[4*g+0] | ((uint32_t)bx[4*g+1] << 16);
        uint32_t w1 = (uint32_t)bx[4*g+2] | ((uint32_t)bx[4*g+3] << 16);
        sts64(sB + ((kobase + 8u * g) ^ pswz), w0, w1);
    }
}

// ---------------------------------------------------------------------------
// MMA consumer on one 32-k chunk.
// stage: [A rows 0-127 8K][A rows 128-255 8K][B 8K]
// ---------------------------------------------------------------------------
__device__ __forceinline__ void mma_chunk(
    uint32_t bufb, float (&acc)[4][4][4],
    uint32_t aRowOff, uint32_t aKext, uint32_t aSwz,
    uint32_t bRowOff, uint32_t bKext, uint32_t bSwz)
{
    #pragma unroll
    for (int kb = 0; kb < 2; ++kb) {
        const uint32_t kb2 = (uint32_t)kb * 32;
        const uint32_t aK = (kb2 + aKext) ^ aSwz;
        const uint32_t bK = (kb2 + bKext) ^ bSwz;

        uint32_t bh[8];
        const uint32_t bAddr = bufb + OFF_B + bRowOff + bK;
        ldsm4(bAddr,        bh[0], bh[1], bh[2], bh[3]);
        ldsm4(bAddr + 1024, bh[4], bh[5], bh[6], bh[7]);

        uint32_t a[16];
        const uint32_t aAddr = bufb + aRowOff + aK;
        #pragma unroll
        for (int am = 0; am < 4; ++am)
            ldsm4(aAddr + am * 1024, a[4*am], a[4*am+1], a[4*am+2], a[4*am+3]);

        #pragma unroll
        for (int am = 0; am < 4; ++am)
            #pragma unroll
            for (int an = 0; an < 4; ++an)
                mma_f16(acc[am][an], a + 4*am, bh[2*an], bh[2*an+1]);
    }
}

// ---------------------------------------------------------------------------
__global__ void __launch_bounds__(512, 1)
conv_mma_kernel(float* __restrict__ out)
{
    extern __shared__ char smem[];
    const uint32_t sb = smem_u32(smem);
    const int tid = threadIdx.x;
    const int bm = blockIdx.x;        // 0..1 (256 rows each), fastest
    const int bn = blockIdx.y;        // 0..728

    // im2col k -> x-offset table
    for (int k = tid; k < KTOT; k += 512) {
        int ci = k / 9, r9 = k - ci * 9;
        int kh = r9 / 3, kw = r9 - kh * 3;
        *(uint32_t*)(smem + OFF_KOFF + k * 4) = (uint32_t)(ci * 3136 + kh * 56 + kw);
    }

    // A copy: two 128-row blocks (mt = 2bm, 2bm+1); 32B per thread per chunk
    const unsigned char* aBase = g_asplit
        + ((size_t)(2 * bm + (tid >> 8)) * 72) * A_SUB + (size_t)(tid & 255) * 32;
    const uint32_t aOff = (uint32_t)(tid >> 8) * A_SUB + (uint32_t)(tid & 255) * 32;

    // B producer invariants
    const int prow = tid >> 2, kq = tid & 3;
    const int ng = bn * 128 + prow;
    const int bimg = ng / NPIMG;
    const int prem = ng - bimg * NPIMG;
    const int oh = prem / 54, ow = prem - oh * 54;
    const __half* xb = g_xh + (size_t)bimg * XIMG + oh * 56 + ow;
    const uint32_t pswz = (uint32_t)((prow >> 1) & 3) << 4;
    const uint32_t koffs = sb + OFF_KOFF;

    // MMA invariants: warp grid 4(m) x 4(n)
    const int lane = tid & 31, wid = tid >> 5;
    const int wm = wid & 3, wn = wid >> 2;
    const uint32_t aRowOff = (uint32_t)(wm >> 1) * A_SUB
                           + (uint32_t)((wm & 1) * 64 + (lane & 15)) * 64;
    const uint32_t aKext   = (uint32_t)(lane >> 4) << 4;
    const uint32_t aSwz    = (uint32_t)(((lane & 15) >> 1) & 3) << 4;
    const uint32_t bRowOff = (uint32_t)(wn * 32 + (lane & 7) + ((lane >> 4) << 3)) * 64;
    const uint32_t bKext   = (uint32_t)((lane >> 3) & 1) << 4;
    const uint32_t bSwz    = (uint32_t)(((lane & 7) >> 1) & 3) << 4;

    float acc[4][4][4];
    #pragma unroll
    for (int i = 0; i < 4; ++i)
        #pragma unroll
        for (int j = 0; j < 4; ++j)
            #pragma unroll
            for (int r = 0; r < 4; ++r) acc[i][j][r] = 0.0f;

    __syncthreads();                      // koff table ready

    // prologue: stage 0
    cpasync16(sb + aOff,      aBase);
    cpasync16(sb + aOff + 16, aBase + 16);
    cp_commit();
    {
        uint16_t bx0[8];
        load_b(0, xb, koffs, kq, bx0);
        store_b(sb, bx0, prow, kq, pswz);
    }
    cp_wait0();
    __syncthreads();

    for (int ch = 0; ch < KCH; ++ch) {
        const uint32_t cur = sb + (uint32_t)(ch & 1) * STAGE_BYTES;
        const uint32_t nxt = sb + (uint32_t)((ch + 1) & 1) * STAGE_BYTES;
        const bool pre = (ch + 1 < KCH);

        uint16_t bx[8];
        if (pre) {
            load_b(ch + 1, xb, koffs, kq, bx);         // LDGs issue, no wait
            const unsigned char* aSrc = aBase + (size_t)(ch + 1) * A_SUB;
            cpasync16(nxt + aOff,      aSrc);
            cpasync16(nxt + aOff + 16, aSrc + 16);
            cp_commit();
        }

        mma_chunk(cur, acc, aRowOff, aKext, aSwz, bRowOff, bKext, bSwz);

        if (pre)
            store_b(nxt, bx, prow, kq, pswz);          // LDGs landed during MMA
        cp_wait0();
        __syncthreads();
    }

    // epilogue: scale by 1/64; acc[am][an] rows co, co+8 ; cols gn, gn+1
    const float s = 0.015625f;
    const int lane4 = lane >> 2, lane2 = (lane & 3) * 2;
    #pragma unroll
    for (int an = 0; an < 4; ++an) {
        const int gn = bn * 128 + wn * 32 + an * 8 + lane2;
        const int b2 = gn / NPIMG;
        const int r2 = gn - b2 * NPIMG;
        float* op = out + (size_t)b2 * OUTIMG + r2;
        #pragma unroll
        for (int am = 0; am < 4; ++am) {
            const int co = bm * 256 + wm * 64 + am * 16 + lane4;
            *(float2*)(op + (size_t)co * NPIMG) =
                make_float2(acc[am][an][0] * s, acc[am][an][1] * s);
            *(float2*)(op + (size_t)(co + 8) * NPIMG) =
                make_float2(acc[am][an][2] * s, acc[am][an][3] * s);
        }
    }
}

// ---------------------------------------------------------------------------
extern "C" void kernel_launch(void* const* d_in, const int* in_sizes, int n_in,
                              void* d_out, int out_size)
{
    const float* x = (const float*)d_in[0];   // [32,256,56,56]
    const float* w = (const float*)d_in[1];   // [512,256,3,3]
    float* out = (float*)d_out;               // [32,512,54,54]

    cudaFuncSetAttribute(conv_mma_kernel,
                         cudaFuncAttributeMaxDynamicSharedMemorySize, SMEM_BYTES);

    pack_x_kernel<<<25088, 256>>>(x);
    prep_a<<<576, 256>>>(w);
    conv_mma_kernel<<<dim3(2, 729), 512, SMEM_BYTES>>>(out);
}

// round 12
// speedup vs baseline: 1.0789x; 1.0789x over previous
#include <cuda_runtime.h>
#include <cuda_fp16.h>
#include <cstdint>

// ============================================================================
// Single-term fp16 mma.sync implicit-GEMM conv, round 12 (= round-8 champion
// + streaming output stores + fused prep; evict_last removed -- illegal on
// scalar loads for this target).
// D = ah*bh ; A = w*64 fp16 (epilogue * 1/64), B = x fp16, rel_err ~2.9e-4.
// Pipeline: LDG_B(ch+1) -> cp.async_A(ch+1) -> MMA(ch) -> STS_B(ch+1) -> sync.
// ============================================================================

#define KTOT   2304
#define KCH    72            // 2304 / 32
#define NPIMG  2916
#define OUTIMG (512*NPIMG)
#define XIMG   (256*3136)

#define A_TILE      8192     // single fp16 plane, 128 rows x 64B
#define STAGE_BYTES 16384    // A 8KB + B 8KB
#define OFF_B       8192
#define OFF_KOFF    32768                  // after 2 stages
#define SMEM_BYTES  (OFF_KOFF + KTOT*4)    // 41984

// A (scaled x64, fp16) in exact swizzled smem-tile layout: [mt(4)][ch(72)][8KB]
__device__ __align__(16) unsigned char g_asplit[4ull*72*8192];    // 2.4MB
// x as fp16
__device__ __align__(16) __half g_xh[32 * 256 * 56 * 56];         // 51.4MB

// ---------------------------------------------------------------------------
__device__ __forceinline__ uint32_t smem_u32(const void* p) {
    uint32_t a;
    asm("{ .reg .u64 t; cvta.to.shared.u64 t, %1; cvt.u32.u64 %0, t; }"
        : "=r"(a) : "l"(p));
    return a;
}
__device__ __forceinline__ void sts64(uint32_t addr, uint32_t a, uint32_t b) {
    asm volatile("st.shared.v2.b32 [%0], {%1, %2};" :: "r"(addr), "r"(a), "r"(b));
}
__device__ __forceinline__ void ldsm4(uint32_t a, uint32_t& r0, uint32_t& r1,
                                      uint32_t& r2, uint32_t& r3) {
    asm volatile("ldmatrix.sync.aligned.m8n8.x4.shared.b16 {%0,%1,%2,%3}, [%4];"
                 : "=r"(r0), "=r"(r1), "=r"(r2), "=r"(r3) : "r"(a));
}
__device__ __forceinline__ void mma_f16(float* c, const uint32_t* a,
                                        uint32_t b0, uint32_t b1) {
    asm volatile(
        "mma.sync.aligned.m16n8k16.row.col.f32.f16.f16.f32 "
        "{%0,%1,%2,%3}, {%4,%5,%6,%7}, {%8,%9}, {%0,%1,%2,%3};"
        : "+f"(c[0]), "+f"(c[1]), "+f"(c[2]), "+f"(c[3])
        : "r"(a[0]), "r"(a[1]), "r"(a[2]), "r"(a[3]), "r"(b0), "r"(b1));
}
__device__ __forceinline__ void cpasync16(uint32_t dst, const void* src) {
    asm volatile("cp.async.cg.shared.global [%0], [%1], 16;"
                 :: "r"(dst), "l"(src) : "memory");
}
__device__ __forceinline__ void cp_commit() {
    asm volatile("cp.async.commit_group;" ::: "memory");
}
__device__ __forceinline__ void cp_wait0() {
    asm volatile("cp.async.wait_group 0;" ::: "memory");
}
// B gather load: read-only data path (plain nc; evict hints illegal on u16)
__device__ __forceinline__ uint16_t ldg_b(const __half* p) {
    uint16_t v;
    asm volatile("ld.global.nc.u16 %0, [%1];" : "=h"(v) : "l"(p));
    return v;
}
// streaming output store (evict-first; don't evict g_xh from L2)
__device__ __forceinline__ void stg_cs2(float* p, float a, float b) {
    asm volatile("st.global.cs.v2.f32 [%0], {%1, %2};"
                 :: "l"(p), "f"(a), "f"(b) : "memory");
}

// ---------------------------------------------------------------------------
// fused prep kernel: blocks [0, 25088) pack x -> fp16; [25088, 25664) split A
// ---------------------------------------------------------------------------
__global__ void prep_all(const float* __restrict__ x, const float* __restrict__ w) {
    const int b = blockIdx.x;
    if (b < 25088) {
        int i = b * 256 + threadIdx.x;               // 6422528 total
        float4 v = ((const float4*)x)[i];
        __half h0 = __float2half_rn(v.x), h1 = __float2half_rn(v.y);
        __half h2 = __float2half_rn(v.z), h3 = __float2half_rn(v.w);
        uint32_t w0 = (uint32_t)*(uint16_t*)&h0 | ((uint32_t)*(uint16_t*)&h1 << 16);
        uint32_t w1 = (uint32_t)*(uint16_t*)&h2 | ((uint32_t)*(uint16_t*)&h3 << 16);
        ((uint2*)g_xh)[i] = make_uint2(w0, w1);
    } else {
        int i = (b - 25088) * 256 + threadIdx.x;     // 147456 total
        int co = i / 288;
        int r  = i - co * 288;
        int ch = r >> 2, kq = r & 3;
        const float4* p = (const float4*)(w + (size_t)co * KTOT + ch * 32 + kq * 8);
        float4 v0 = p[0], v1 = p[1];
        __half a0 = __float2half_rn(v0.x * 64.f), a1 = __float2half_rn(v0.y * 64.f);
        __half a2 = __float2half_rn(v0.z * 64.f), a3 = __float2half_rn(v0.w * 64.f);
        __half a4 = __float2half_rn(v1.x * 64.f), a5 = __float2half_rn(v1.y * 64.f);
        __half a6 = __float2half_rn(v1.z * 64.f), a7 = __float2half_rn(v1.w * 64.f);
        uint32_t h0 = (uint32_t)*(uint16_t*)&a0 | ((uint32_t)*(uint16_t*)&a1 << 16);
        uint32_t h1 = (uint32_t)*(uint16_t*)&a2 | ((uint32_t)*(uint16_t*)&a3 << 16);
        uint32_t h2 = (uint32_t)*(uint16_t*)&a4 | ((uint32_t)*(uint16_t*)&a5 << 16);
        uint32_t h3 = (uint32_t)*(uint16_t*)&a6 | ((uint32_t)*(uint16_t*)&a7 << 16);
        int m = co & 127;
        size_t base = ((size_t)(co >> 7) * KCH + ch) * A_TILE
                    + m * 64 + (((uint32_t)kq * 16) ^ ((((uint32_t)m >> 1) & 3) << 4));
        *(uint4*)(g_asplit + base) = make_uint4(h0, h1, h2, h3);
    }
}

// ---------------------------------------------------------------------------
// B producer split: load phase (LDG -> regs) / store phase (regs -> smem)
// ---------------------------------------------------------------------------
__device__ __forceinline__ void load_b(
    int ch, const __half* xb, uint32_t koffs, int khalf, uint16_t (&bx)[16])
{
    const uint32_t kb4 = koffs + (uint32_t)(ch * 32 + khalf * 16) * 4;
    #pragma unroll
    for (int g = 0; g < 4; ++g) {
        uint32_t k0, k1, k2, k3;
        asm volatile("ld.shared.v4.b32 {%0,%1,%2,%3}, [%4];"
                     : "=r"(k0), "=r"(k1), "=r"(k2), "=r"(k3)
                     : "r"(kb4 + g * 16));
        bx[4*g+0] = ldg_b(xb + k0);
        bx[4*g+1] = ldg_b(xb + k1);
        bx[4*g+2] = ldg_b(xb + k2);
        bx[4*g+3] = ldg_b(xb + k3);
    }
}
__device__ __forceinline__ void store_b(
    uint32_t bufb, const uint16_t (&bx)[16], int prow, int khalf, uint32_t pswz)
{
    const uint32_t sB = bufb + OFF_B + (uint32_t)prow * 64;
    const uint32_t kobase = (uint32_t)khalf * 32;
    #pragma unroll
    for (int g = 0; g < 4; ++g) {
        uint32_t w0 = (uint32_t)bx[4*g+0] | ((uint32_t)bx[4*g+1] << 16);
        uint32_t w1 = (uint32_t)bx[4*g+2] | ((uint32_t)bx[4*g+3] << 16);
        sts64(sB + ((kobase + 8u * g) ^ pswz), w0, w1);
    }
}

// ---------------------------------------------------------------------------
// MMA consumer on one 32-k chunk. buf: [A 0][B 8K]
// ---------------------------------------------------------------------------
__device__ __forceinline__ void mma_chunk(
    uint32_t bufb, float (&acc)[4][4][4],
    uint32_t aRowOff, uint32_t aKext, uint32_t aSwz,
    uint32_t bRowOff, uint32_t bKext, uint32_t bSwz)
{
    #pragma unroll
    for (int kb = 0; kb < 2; ++kb) {
        const uint32_t kb2 = (uint32_t)kb * 32;
        const uint32_t aK = (kb2 + aKext) ^ aSwz;
        const uint32_t bK = (kb2 + bKext) ^ bSwz;

        uint32_t bh[8];
        const uint32_t bAddr = bufb + OFF_B + bRowOff + bK;
        ldsm4(bAddr,        bh[0], bh[1], bh[2], bh[3]);
        ldsm4(bAddr + 1024, bh[4], bh[5], bh[6], bh[7]);

        uint32_t a[16];
        const uint32_t aAddr = bufb + aRowOff + aK;
        #pragma unroll
        for (int am = 0; am < 4; ++am)
            ldsm4(aAddr + am * 1024, a[4*am], a[4*am+1], a[4*am+2], a[4*am+3]);

        #pragma unroll
        for (int am = 0; am < 4; ++am)
            #pragma unroll
            for (int an = 0; an < 4; ++an)
                mma_f16(acc[am][an], a + 4*am, bh[2*an], bh[2*an+1]);
    }
}

// ---------------------------------------------------------------------------
__global__ void __launch_bounds__(256, 2)
conv_mma_kernel(float* __restrict__ out)
{
    extern __shared__ char smem[];
    const uint32_t sb = smem_u32(smem);
    const int tid = threadIdx.x;
    const int bm = blockIdx.x;        // 0..3, fastest -> x gathers shared in L2
    const int bn = blockIdx.y;        // 0..728

    // im2col k -> x-offset table
    for (int k = tid; k < KTOT; k += 256) {
        int ci = k / 9, r9 = k - ci * 9;
        int kh = r9 / 3, kw = r9 - kh * 3;
        *(uint32_t*)(smem + OFF_KOFF + k * 4) = (uint32_t)(ci * 3136 + kh * 56 + kw);
    }

    // A copy: 32B per thread per chunk
    const unsigned char* aBase = g_asplit + (size_t)bm * KCH * A_TILE
                               + (size_t)tid * 32;
    const uint32_t aOff = (uint32_t)tid * 32;

    // B producer invariants
    const int prow = tid >> 1, khalf = tid & 1;
    const int ng = bn * 128 + prow;
    const int bimg = ng / NPIMG;
    const int prem = ng - bimg * NPIMG;
    const int oh = prem / 54, ow = prem - oh * 54;
    const __half* xb = g_xh + (size_t)bimg * XIMG + oh * 56 + ow;
    const uint32_t pswz = (uint32_t)((prow >> 1) & 3) << 4;
    const uint32_t koffs = sb + OFF_KOFF;

    // MMA invariants: warp grid 2(m) x 4(n)
    const int lane = tid & 31, wid = tid >> 5;
    const int wm = wid & 1, wn = wid >> 1;
    const uint32_t aRowOff = (uint32_t)(wm * 64 + (lane & 15)) * 64;
    const uint32_t aKext   = (uint32_t)(lane >> 4) << 4;
    const uint32_t aSwz    = (uint32_t)(((lane & 15) >> 1) & 3) << 4;
    const uint32_t bRowOff = (uint32_t)(wn * 32 + (lane & 7) + ((lane >> 4) << 3)) * 64;
    const uint32_t bKext   = (uint32_t)((lane >> 3) & 1) << 4;
    const uint32_t bSwz    = (uint32_t)(((lane & 7) >> 1) & 3) << 4;

    float acc[4][4][4];
    #pragma unroll
    for (int i = 0; i < 4; ++i)
        #pragma unroll
        for (int j = 0; j < 4; ++j)
            #pragma unroll
            for (int r = 0; r < 4; ++r) acc[i][j][r] = 0.0f;

    __syncthreads();                      // koff table ready

    // prologue: stage 0
    cpasync16(sb + aOff,      aBase);
    cpasync16(sb + aOff + 16, aBase + 16);
    cp_commit();
    {
        uint16_t bx0[16];
        load_b(0, xb, koffs, khalf, bx0);
        store_b(sb, bx0, prow, khalf, pswz);
    }
    cp_wait0();
    __syncthreads();

    for (int ch = 0; ch < KCH; ++ch) {
        const uint32_t cur = sb + (uint32_t)(ch & 1) * STAGE_BYTES;
        const uint32_t nxt = sb + (uint32_t)((ch + 1) & 1) * STAGE_BYTES;
        const bool pre = (ch + 1 < KCH);

        uint16_t bx[16];
        if (pre) {
            load_b(ch + 1, xb, koffs, khalf, bx);      // LDGs issue, no wait
            const unsigned char* aSrc = aBase + (size_t)(ch + 1) * A_TILE;
            cpasync16(nxt + aOff,      aSrc);
            cpasync16(nxt + aOff + 16, aSrc + 16);
            cp_commit();
        }

        mma_chunk(cur, acc, aRowOff, aKext, aSwz, bRowOff, bKext, bSwz);

        if (pre)
            store_b(nxt, bx, prow, khalf, pswz);       // LDGs landed during MMA
        cp_wait0();
        __syncthreads();
    }

    // epilogue: scale by 1/64; streaming stores (evict-first)
    const float s = 0.015625f;
    const int lane4 = lane >> 2, lane2 = (lane & 3) * 2;
    #pragma unroll
    for (int an = 0; an < 4; ++an) {
        const int gn = bn * 128 + wn * 32 + an * 8 + lane2;
        const int b2 = gn / NPIMG;
        const int r2 = gn - b2 * NPIMG;
        float* op = out + (size_t)b2 * OUTIMG + r2;
        #pragma unroll
        for (int am = 0; am < 4; ++am) {
            const int co = bm * 128 + wm * 64 + am * 16 + lane4;
            stg_cs2(op + (size_t)co * NPIMG,
                    acc[am][an][0] * s, acc[am][an][1] * s);
            stg_cs2(op + (size_t)(co + 8) * NPIMG,
                    acc[am][an][2] * s, acc[am][an][3] * s);
        }
    }
}

// ---------------------------------------------------------------------------
extern "C" void kernel_launch(void* const* d_in, const int* in_sizes, int n_in,
                              void* d_out, int out_size)
{
    const float* x = (const float*)d_in[0];   // [32,256,56,56]
    const float* w = (const float*)d_in[1];   // [512,256,3,3]
    float* out = (float*)d_out;               // [32,512,54,54]

    cudaFuncSetAttribute(conv_mma_kernel,
                         cudaFuncAttributeMaxDynamicSharedMemorySize, SMEM_BYTES);

    prep_all<<<25664, 256>>>(x, w);           // fused pack_x + prep_a
    conv_mma_kernel<<<dim3(4, 729), 256, SMEM_BYTES>>>(out);
}